// round 11
// baseline (speedup 1.0000x reference)
#include <cuda_runtime.h>
#include <cuda_bf16.h>

#define HW     8192
#define THRESH 0.5f
#define TX     128      // output tile cols per block
#define TY     64       // output tile rows per block
#define IN_H   72       // h rows per tile (TY + 8 halo)
#define H_PAD  128      // h_s row stride (row-major, conflict-free both phases)
#define NTHREADS 256

#define SMEM_BYTES (IN_H * H_PAD * (int)sizeof(float))   // 36864 B

__device__ __forceinline__ float4 thresh4(float4 v) {
    v.x = (v.x > THRESH) ? v.x : 0.f;
    v.y = (v.y > THRESH) ? v.y : 0.f;
    v.z = (v.z > THRESH) ? v.z : 0.f;
    v.w = (v.w > THRESH) ? v.w : 0.f;
    return v;
}

// encode flag (h==ctr) into sign bit; h >= 0 post-threshold, so -h (or -0.0)
// carries the flag and fabsf recovers the magnitude.
__device__ __forceinline__ float enc(float h, float ctr) {
    return (h == ctr) ? -h : h;
}

// peak iff vertical max mp equals |s| AND sign flag set AND positive
__device__ __forceinline__ float peak1(float mp, float s) {
    const bool flag = (__float_as_int(s) & 0x80000000) != 0;
    return (mp > 0.f && mp == fabsf(s) && flag) ? mp : 0.f;
}

__device__ __forceinline__ float4 shfl_up4(float4 v) {
    float4 r;
    r.x = __shfl_up_sync(0xffffffffu, v.x, 1);
    r.y = __shfl_up_sync(0xffffffffu, v.y, 1);
    r.z = __shfl_up_sync(0xffffffffu, v.z, 1);
    r.w = __shfl_up_sync(0xffffffffu, v.w, 1);
    return r;
}
__device__ __forceinline__ float4 shfl_dn4(float4 v) {
    float4 r;
    r.x = __shfl_down_sync(0xffffffffu, v.x, 1);
    r.y = __shfl_down_sync(0xffffffffu, v.y, 1);
    r.z = __shfl_down_sync(0xffffffffu, v.z, 1);
    r.w = __shfl_down_sync(0xffffffffu, v.w, 1);
    return r;
}

__global__ void __launch_bounds__(NTHREADS, 4)
postprocess_kernel(const float* __restrict__ in, float* __restrict__ out)
{
    extern __shared__ float h_s[];      // [IN_H][H_PAD] row-major

    const int bx = blockIdx.x;          // 0..63
    const int by = blockIdx.y;          // 0..127
    const int tid  = threadIdx.x;
    const int warp = tid >> 5;          // 0..7
    const int lane = tid & 31;

    const int gr0 = by * TY - 4;        // first h row in global coords
    const int cb0 = bx * TX;            // first output col of tile

    // -------- Phase A: one warp per row; fully coalesced LDG + shfl halo ---
    // Each lane owns output cols 4*lane .. 4*lane+3.
#pragma unroll
    for (int it = 0; it < 9; it++) {            // 72 rows / 8 warps
        const int row = warp + 8 * it;
        const int gr  = gr0 + row;
        float4 o;
        if ((unsigned)gr < (unsigned)HW) {
            const float* rp = in + (size_t)gr * HW + cb0;
            // main quad: coalesced
            const float4 v = thresh4(*reinterpret_cast<const float4*>(&rp[4 * lane]));
            // neighbor quads via register exchange
            float4 LQ = shfl_up4(v);
            float4 RQ = shfl_dn4(v);
            if (lane == 0) {
                LQ = (bx > 0)
                   ? thresh4(*reinterpret_cast<const float4*>(&rp[-4]))
                   : make_float4(0.f, 0.f, 0.f, 0.f);
            }
            if (lane == 31) {
                RQ = (bx < 63)
                   ? thresh4(*reinterpret_cast<const float4*>(&rp[TX]))
                   : make_float4(0.f, 0.f, 0.f, 0.f);
            }
            // suffix maxes of left quad
            const float s3 = LQ.w;
            const float s2 = fmaxf(LQ.z, s3);
            const float s1 = fmaxf(LQ.y, s2);
            const float s0 = fmaxf(LQ.x, s1);
            // full max of own quad
            const float M = fmaxf(fmaxf(v.x, v.y), fmaxf(v.z, v.w));
            // prefix maxes of right quad
            const float p0 = RQ.x;
            const float p1 = fmaxf(p0, RQ.y);
            const float p2 = fmaxf(p1, RQ.z);
            const float p3 = fmaxf(p2, RQ.w);
            o.x = enc(fmaxf(fmaxf(s0, M), p0), v.x);
            o.y = enc(fmaxf(fmaxf(s1, M), p1), v.y);
            o.z = enc(fmaxf(fmaxf(s2, M), p2), v.z);
            o.w = enc(fmaxf(fmaxf(s3, M), p3), v.w);
        } else {
            o = make_float4(0.f, 0.f, 0.f, 0.f);
        }
        *reinterpret_cast<float4*>(&h_s[row * H_PAD + 4 * lane]) = o;
    }
    __syncthreads();

    // -------- Phase B: vertical 9-max, 1 col/thread, 32-row strips --------
    // 256 tasks: col 0..127 x strip 0..1. 5 blocks of 8 h rows (Gil-Werman):
    // reads 40 h rows per 32 outputs (amp 1.25x), conflict-free scalar LDS,
    // coalesced scalar STG down the column.
    {
        const int c = tid & 127;            // local output col
        const int s = tid >> 7;             // strip 0/1
        const int r0 = s * 32;
        const float* hp = &h_s[r0 * H_PAD + c];
        float* op = out + (size_t)(by * TY + r0) * HW + (size_t)(cb0 + c);

        float S[8], rawt[4], C[8];
        // Block 0 (h rows r0..r0+7): suffix maxes of |.|, keep raw tail
        {
#pragma unroll
            for (int j = 0; j < 8; j++) C[j] = hp[j * H_PAD];
#pragma unroll
            for (int k = 0; k < 4; k++) rawt[k] = C[4 + k];
            S[7] = fabsf(C[7]);
#pragma unroll
            for (int j = 6; j >= 0; j--) S[j] = fmaxf(fabsf(C[j]), S[j + 1]);
        }
        // Stream 4 blocks of 8, each emits 8 output rows
#pragma unroll
        for (int k = 1; k <= 4; k++) {
#pragma unroll
            for (int j = 0; j < 8; j++) C[j] = hp[(8 * k + j) * H_PAD];
            float P = fabsf(C[0]);
#pragma unroll
            for (int i = 0; i < 8; i++) {
                if (i > 0) P = fmaxf(P, fabsf(C[i]));
                const float mp = fmaxf(S[i], P);          // 9-tap vertical max
                const float cs = (i < 4) ? rawt[i] : C[i - 4];
                op[(size_t)(8 * (k - 1) + i) * HW] = peak1(mp, cs);
            }
#pragma unroll
            for (int t = 0; t < 4; t++) rawt[t] = C[4 + t];
            S[7] = fabsf(C[7]);
#pragma unroll
            for (int j = 6; j >= 0; j--) S[j] = fmaxf(fabsf(C[j]), S[j + 1]);
        }
    }
}

extern "C" void kernel_launch(void* const* d_in, const int* in_sizes, int n_in,
                              void* d_out, int out_size)
{
    const float* in = (const float*)d_in[0];
    float* out = (float*)d_out;

    static bool attr_set = false;
    if (!attr_set) {
        cudaFuncSetAttribute(postprocess_kernel,
                             cudaFuncAttributeMaxDynamicSharedMemorySize,
                             SMEM_BYTES);
        attr_set = true;
    }

    dim3 grid(HW / TX, HW / TY);   // 64 x 128
    postprocess_kernel<<<grid, NTHREADS, SMEM_BYTES>>>(in, out);
}

// round 12
// speedup vs baseline: 1.3822x; 1.3822x over previous
#include <cuda_runtime.h>
#include <cuda_bf16.h>

#define HW     8192
#define THRESH 0.5f
#define TX     128      // output tile cols per block
#define TY     64       // output tile rows per block
#define IN_H   72       // h rows per tile (TY + 8 halo)
#define H_PAD  128      // h_s row stride (row-major, conflict-free both phases)
#define NTHREADS 256

#define SMEM_BYTES (IN_H * H_PAD * (int)sizeof(float))   // 36864 B

__device__ __forceinline__ float4 thresh4(float4 v) {
    v.x = (v.x > THRESH) ? v.x : 0.f;
    v.y = (v.y > THRESH) ? v.y : 0.f;
    v.z = (v.z > THRESH) ? v.z : 0.f;
    v.w = (v.w > THRESH) ? v.w : 0.f;
    return v;
}

// encode flag (h==ctr) into sign bit; h >= 0 post-threshold, so -h (or -0.0)
// carries the flag and fabsf recovers the magnitude.
__device__ __forceinline__ float enc(float h, float ctr) {
    return (h == ctr) ? -h : h;
}

// peak iff vertical max mp equals |s| AND sign flag set. (mp==0 case emits
// mp==0 anyway, so no positivity test needed.)
__device__ __forceinline__ float peak1(float mp, float s) {
    const bool flag = (__float_as_int(s) & 0x80000000) != 0;
    return (mp == fabsf(s) && flag) ? mp : 0.f;
}

__global__ void __launch_bounds__(NTHREADS, 4)
postprocess_kernel(const float* __restrict__ in, float* __restrict__ out)
{
    extern __shared__ float h_s[];      // [IN_H][H_PAD] row-major

    const int bx = blockIdx.x;          // 0..63
    const int by = blockIdx.y;          // 0..127
    const int tid  = threadIdx.x;
    const int warp = tid >> 5;          // 0..7
    const int lane = tid & 31;

    const int gr0 = by * TY - 4;        // first h row in global coords
    const int cb0 = bx * TX;            // first output col of tile

    // Branch-free halo offsets: only lane 0 @ bx==0 and lane 31 @ bx==63
    // would read out of bounds; clamp the offset and select-zero the value.
    const bool lok = !(bx == 0 && lane == 0);
    const bool rok = !(bx == 63 && lane == 31);
    const int  lofs = lok ? (4 * lane - 4) : 0;
    const int  rofs = rok ? (4 * lane + 4) : (4 * lane);

    // -------- Phase A: one warp per row; 3 coalesced LDGs, double-buffered -
    // Lane l owns output cols 4l..4l+3; halo quads via shifted coalesced LDGs
    // (L1 hits on the overlap). Rows outside the image: clamped-row load +
    // select-zero (branch-free).
    float4 V, L, R, nV, nL, nR;
    {   // prime iteration 0
        const int gr  = gr0 + warp;
        const int grc = min(max(gr, 0), HW - 1);
        const float* rp = in + (size_t)grc * HW + cb0;
        const bool rin = (unsigned)gr < (unsigned)HW;
        const float4 z = make_float4(0.f, 0.f, 0.f, 0.f);
        V = rin         ? thresh4(*reinterpret_cast<const float4*>(&rp[4 * lane])) : z;
        L = (rin && lok) ? thresh4(*reinterpret_cast<const float4*>(&rp[lofs]))    : z;
        R = (rin && rok) ? thresh4(*reinterpret_cast<const float4*>(&rp[rofs]))    : z;
    }
#pragma unroll
    for (int it = 0; it < 9; it++) {            // 72 rows / 8 warps
        if (it < 8) {                            // prefetch next row
            const int gr  = gr0 + warp + 8 * (it + 1);
            const int grc = min(max(gr, 0), HW - 1);
            const float* rp = in + (size_t)grc * HW + cb0;
            const bool rin = (unsigned)gr < (unsigned)HW;
            const float4 z = make_float4(0.f, 0.f, 0.f, 0.f);
            nV = rin         ? thresh4(*reinterpret_cast<const float4*>(&rp[4 * lane])) : z;
            nL = (rin && lok) ? thresh4(*reinterpret_cast<const float4*>(&rp[lofs]))    : z;
            nR = (rin && rok) ? thresh4(*reinterpret_cast<const float4*>(&rp[rofs]))    : z;
        }
        // horizontal 9-max from L | V | R
        const float s3 = L.w;
        const float s2 = fmaxf(L.z, s3);
        const float s1 = fmaxf(L.y, s2);
        const float s0 = fmaxf(L.x, s1);
        const float M  = fmaxf(fmaxf(V.x, V.y), fmaxf(V.z, V.w));
        const float p0 = R.x;
        const float p1 = fmaxf(p0, R.y);
        const float p2 = fmaxf(p1, R.z);
        const float p3 = fmaxf(p2, R.w);
        float4 o;
        o.x = enc(fmaxf(fmaxf(s0, M), p0), V.x);
        o.y = enc(fmaxf(fmaxf(s1, M), p1), V.y);
        o.z = enc(fmaxf(fmaxf(s2, M), p2), V.z);
        o.w = enc(fmaxf(fmaxf(s3, M), p3), V.w);
        const int row = warp + 8 * it;
        *reinterpret_cast<float4*>(&h_s[row * H_PAD + 4 * lane]) = o;
        V = nV; L = nL; R = nR;
    }
    __syncthreads();

    // -------- Phase B: vertical 9-max, 1 col/thread, 32-row strips --------
    // 256 tasks: col 0..127 x strip 0..1. 5 blocks of 8 h rows (Gil-Werman):
    // reads 40 h rows per 32 outputs (amp 1.25x), conflict-free scalar LDS
    // (consecutive lanes -> consecutive banks), coalesced scalar STG.
    {
        const int c = tid & 127;            // local output col
        const int s = tid >> 7;             // strip 0/1
        const int r0 = s * 32;
        const float* hp = &h_s[r0 * H_PAD + c];
        float* op = out + (size_t)(by * TY + r0) * HW + (size_t)(cb0 + c);

        float S[8], rawt[4], C[8];
        // Block 0 (h rows r0..r0+7): suffix maxes of |.|, keep raw tail
        {
#pragma unroll
            for (int j = 0; j < 8; j++) C[j] = hp[j * H_PAD];
#pragma unroll
            for (int k = 0; k < 4; k++) rawt[k] = C[4 + k];
            S[7] = fabsf(C[7]);
#pragma unroll
            for (int j = 6; j >= 0; j--) S[j] = fmaxf(fabsf(C[j]), S[j + 1]);
        }
        // Stream 4 blocks of 8, each emits 8 output rows
#pragma unroll
        for (int k = 1; k <= 4; k++) {
#pragma unroll
            for (int j = 0; j < 8; j++) C[j] = hp[(8 * k + j) * H_PAD];
            float P = fabsf(C[0]);
#pragma unroll
            for (int i = 0; i < 8; i++) {
                if (i > 0) P = fmaxf(P, fabsf(C[i]));
                const float mp = fmaxf(S[i], P);          // 9-tap vertical max
                const float cs = (i < 4) ? rawt[i] : C[i - 4];
                op[(size_t)(8 * (k - 1) + i) * HW] = peak1(mp, cs);
            }
#pragma unroll
            for (int t = 0; t < 4; t++) rawt[t] = C[4 + t];
            S[7] = fabsf(C[7]);
#pragma unroll
            for (int j = 6; j >= 0; j--) S[j] = fmaxf(fabsf(C[j]), S[j + 1]);
        }
    }
}

extern "C" void kernel_launch(void* const* d_in, const int* in_sizes, int n_in,
                              void* d_out, int out_size)
{
    const float* in = (const float*)d_in[0];
    float* out = (float*)d_out;

    static bool attr_set = false;
    if (!attr_set) {
        cudaFuncSetAttribute(postprocess_kernel,
                             cudaFuncAttributeMaxDynamicSharedMemorySize,
                             SMEM_BYTES);
        attr_set = true;
    }

    dim3 grid(HW / TX, HW / TY);   // 64 x 128
    postprocess_kernel<<<grid, NTHREADS, SMEM_BYTES>>>(in, out);
}

// round 13
// speedup vs baseline: 1.5325x; 1.1088x over previous
#include <cuda_runtime.h>
#include <cuda_bf16.h>

#define HW     8192
#define THRESH 0.5f
#define TX     128      // output tile cols per block
#define TY     64       // output tile rows per block
#define IN_H   72       // h rows per tile (TY + 8 halo)
#define H_PAD  128      // h_s row stride (row-major, conflict-free both phases)
#define NTHREADS 256

#define SMEM_BYTES (IN_H * H_PAD * (int)sizeof(float))   // 36864 B

// Raw-domain trick: thresh(x) = x*[x>0.5] is monotone, so
// maxpool(thresh(X)) == thresh(maxpool(X)) and the peak test becomes
//   conf = mpraw  iff  mpraw > 0.5  &&  mpraw == ctr_raw
// on RAW values (inputs are >= 0; zero-padding at borders is safe).
// Phase A encodes (hraw == ctr_raw) into the sign bit of hraw.

template<bool EDGE>
__device__ __forceinline__ void phaseA(const float* __restrict__ in,
                                       float* __restrict__ h_s,
                                       int gr0, int cb0, int warp, int lane, int bx)
{
    const float4 z = make_float4(0.f, 0.f, 0.f, 0.f);
    const bool lok = !EDGE || !(bx == 0 && lane == 0);
    const bool rok = !EDGE || !(bx == 63 && lane == 31);
    const int  lofs = (EDGE && !lok) ? 0 : (4 * lane - 4);
    const int  rofs = (EDGE && !rok) ? (4 * lane) : (4 * lane + 4);

    float4 V, L, R, nV, nL, nR;
    {   // prime iteration 0 (rin is warp-uniform)
        const int gr = gr0 + warp;
        if ((unsigned)gr < (unsigned)HW) {
            const float* rp = in + (size_t)gr * HW + cb0;
            V = *reinterpret_cast<const float4*>(&rp[4 * lane]);
            L = (!EDGE || lok) ? *reinterpret_cast<const float4*>(&rp[lofs]) : z;
            R = (!EDGE || rok) ? *reinterpret_cast<const float4*>(&rp[rofs]) : z;
        } else { V = z; L = z; R = z; }
    }
#pragma unroll
    for (int it = 0; it < 9; it++) {            // 72 rows / 8 warps
        if (it < 8) {                            // prefetch next row (uniform branch)
            const int gr = gr0 + warp + 8 * (it + 1);
            if ((unsigned)gr < (unsigned)HW) {
                const float* rp = in + (size_t)gr * HW + cb0;
                nV = *reinterpret_cast<const float4*>(&rp[4 * lane]);
                nL = (!EDGE || lok) ? *reinterpret_cast<const float4*>(&rp[lofs]) : z;
                nR = (!EDGE || rok) ? *reinterpret_cast<const float4*>(&rp[rofs]) : z;
            } else { nV = z; nL = z; nR = z; }
        }
        // horizontal 9-max on RAW values from L | V | R
        const float s3 = L.w;
        const float s2 = fmaxf(L.z, s3);
        const float s1 = fmaxf(L.y, s2);
        const float s0 = fmaxf(L.x, s1);
        const float M  = fmaxf(fmaxf(V.x, V.y), fmaxf(V.z, V.w));
        const float p0 = R.x;
        const float p1 = fmaxf(p0, R.y);
        const float p2 = fmaxf(p1, R.z);
        const float p3 = fmaxf(p2, R.w);
        const float hx = fmaxf(fmaxf(s0, M), p0);
        const float hy = fmaxf(fmaxf(s1, M), p1);
        const float hz = fmaxf(fmaxf(s2, M), p2);
        const float hw = fmaxf(fmaxf(s3, M), p3);
        float4 o;   // sign bit = (h == center): h >= 0 so -h / -0.0 carries it
        o.x = (hx == V.x) ? -hx : hx;
        o.y = (hy == V.y) ? -hy : hy;
        o.z = (hz == V.z) ? -hz : hz;
        o.w = (hw == V.w) ? -hw : hw;
        const int row = warp + 8 * it;
        *reinterpret_cast<float4*>(&h_s[row * H_PAD + 4 * lane]) = o;
        V = nV; L = nL; R = nR;
    }
}

__global__ void __launch_bounds__(NTHREADS, 4)
postprocess_kernel(const float* __restrict__ in, float* __restrict__ out)
{
    extern __shared__ float h_s[];      // [IN_H][H_PAD] row-major

    const int bx = blockIdx.x;          // 0..63
    const int by = blockIdx.y;          // 0..127
    const int tid  = threadIdx.x;
    const int warp = tid >> 5;          // 0..7
    const int lane = tid & 31;

    const int gr0 = by * TY - 4;        // first h row in global coords
    const int cb0 = bx * TX;            // first output col of tile

    // -------- Phase A: one warp per row; 3 coalesced LDGs, double-buffered
    if (bx > 0 && bx < 63)
        phaseA<false>(in, h_s, gr0, cb0, warp, lane, bx);
    else
        phaseA<true>(in, h_s, gr0, cb0, warp, lane, bx);
    __syncthreads();

    // -------- Phase B: vertical 9-max, 1 col/thread, 32-row strips --------
    // 256 tasks: col 0..127 x strip 0..1. 5 blocks of 8 h rows (Gil-Werman):
    // reads 40 h rows per 32 outputs (amp 1.25x), conflict-free scalar LDS,
    // coalesced scalar STG down the column.
    {
        const int c = tid & 127;            // local output col
        const int s = tid >> 7;             // strip 0/1
        const int r0 = s * 32;
        const float* hp = &h_s[r0 * H_PAD + c];
        float* op = out + (size_t)(by * TY + r0) * HW + (size_t)(cb0 + c);

        float S[8], rawt[4], C[8];
        // Block 0 (h rows r0..r0+7): suffix maxes of |.|, keep raw tail
        {
#pragma unroll
            for (int j = 0; j < 8; j++) C[j] = hp[j * H_PAD];
#pragma unroll
            for (int k = 0; k < 4; k++) rawt[k] = C[4 + k];
            S[7] = fabsf(C[7]);
#pragma unroll
            for (int j = 6; j >= 0; j--) S[j] = fmaxf(fabsf(C[j]), S[j + 1]);
        }
        // Stream 4 blocks of 8, each emits 8 output rows
#pragma unroll
        for (int k = 1; k <= 4; k++) {
#pragma unroll
            for (int j = 0; j < 8; j++) C[j] = hp[(8 * k + j) * H_PAD];
            float P = fabsf(C[0]);
#pragma unroll
            for (int i = 0; i < 8; i++) {
                if (i > 0) P = fmaxf(P, fabsf(C[i]));
                const float mp = fmaxf(S[i], P);          // 9-tap vertical max
                const float cs = (i < 4) ? rawt[i] : C[i - 4];
                // peak iff mp == -cs (sign flag + magnitude match) and above thresh
                op[(size_t)(8 * (k - 1) + i) * HW] =
                    (mp == -cs && mp > THRESH) ? mp : 0.f;
            }
#pragma unroll
            for (int t = 0; t < 4; t++) rawt[t] = C[4 + t];
            S[7] = fabsf(C[7]);
#pragma unroll
            for (int j = 6; j >= 0; j--) S[j] = fmaxf(fabsf(C[j]), S[j + 1]);
        }
    }
}

extern "C" void kernel_launch(void* const* d_in, const int* in_sizes, int n_in,
                              void* d_out, int out_size)
{
    const float* in = (const float*)d_in[0];
    float* out = (float*)d_out;

    static bool attr_set = false;
    if (!attr_set) {
        cudaFuncSetAttribute(postprocess_kernel,
                             cudaFuncAttributeMaxDynamicSharedMemorySize,
                             SMEM_BYTES);
        attr_set = true;
    }

    dim3 grid(HW / TX, HW / TY);   // 64 x 128
    postprocess_kernel<<<grid, NTHREADS, SMEM_BYTES>>>(in, out);
}